// round 3
// baseline (speedup 1.0000x reference)
#include <cuda_runtime.h>

#define DIM    128
#define NPROJ  256
#define MTILE  64          // projections per shared tile (32 KB)
#define TPB    256         // threads per block (2 threads per token)
#define TOK_PER_BLOCK (TPB / 2)

// packed f32x2 FMA: d = a*b + c, lane-wise on two packed fp32
__device__ __forceinline__ void fma2(unsigned long long &d,
                                     unsigned long long a,
                                     unsigned long long b,
                                     unsigned long long c) {
    asm("fma.rn.f32x2 %0, %1, %2, %3;" : "=l"(d) : "l"(a), "l"(b), "l"(c));
}

__device__ __forceinline__ float2 unpack2(unsigned long long v) {
    float2 r;
    asm("mov.b64 {%0, %1}, %2;" : "=f"(r.x), "=f"(r.y) : "l"(v));
    return r;
}

__global__ void __launch_bounds__(TPB, 1)
qjl_kernel(const float* __restrict__ Q,
           const float* __restrict__ K,
           const float* __restrict__ S,
           float* __restrict__ out,
           int ntok)
{
    // 64 projections x 128 dims fp32 = 32 KB, stored as 16B (4-float) chunks
    __shared__ ulonglong2 s_sh[MTILE * DIM / 4];

    const int tid  = threadIdx.x;
    const int half = tid & 1;                       // which 64-dim half this thread owns
    const int token = blockIdx.x * TOK_PER_BLOCK + (tid >> 1);
    const int tok_c = token < ntok ? token : (ntok - 1);   // clamp (reads only)

    const ulonglong2* kg = (const ulonglong2*)(K + (size_t)tok_c * DIM + half * 64);
    const ulonglong2* qg = (const ulonglong2*)(Q + (size_t)tok_c * DIM + half * 64);

    // Hold this token's 64-dim halves of k and q in registers as packed f32x2.
    unsigned long long kreg[32], qreg[32];
#pragma unroll
    for (int i = 0; i < 16; ++i) {
        ulonglong2 kv = kg[i]; kreg[2*i] = kv.x; kreg[2*i+1] = kv.y;
        ulonglong2 qv = qg[i]; qreg[2*i] = qv.x; qreg[2*i+1] = qv.y;
    }

    float acc = 0.0f;

    for (int mt = 0; mt < NPROJ; mt += MTILE) {
        __syncthreads();
        // cooperative, coalesced load of the S tile (64 x 128 fp32)
        const ulonglong2* sg = (const ulonglong2*)S + (size_t)mt * (DIM / 4);
        for (int i = tid; i < MTILE * DIM / 4; i += TPB) s_sh[i] = sg[i];
        __syncthreads();

#pragma unroll 2
        for (int ml = 0; ml < MTILE; ++ml) {
            // this thread's 64-dim slice of projection row (mt+ml):
            // broadcast LDS.128 (2 distinct addrs/warp -> conflict-free)
            const ulonglong2* srow = &s_sh[ml * (DIM / 4) + half * 16];

            // 4 independent f32x2 accumulator chains (even/odd pairs, k/q)
            unsigned long long ak0 = 0ull, ak1 = 0ull, aq0 = 0ull, aq1 = 0ull;
#pragma unroll
            for (int i = 0; i < 16; ++i) {
                ulonglong2 sv = srow[i];
                fma2(ak0, sv.x, kreg[2*i],     ak0);
                fma2(aq0, sv.x, qreg[2*i],     aq0);
                fma2(ak1, sv.y, kreg[2*i + 1], ak1);
                fma2(aq1, sv.y, qreg[2*i + 1], aq1);
            }

            float2 k0 = unpack2(ak0), k1 = unpack2(ak1);
            float2 q0 = unpack2(aq0), q1 = unpack2(aq1);
            float kp = (k0.x + k1.x) + (k0.y + k1.y);
            float qp = (q0.x + q1.x) + (q0.y + q1.y);

            // merge the two 64-dim halves (thread pair)
            kp += __shfl_xor_sync(0xffffffffu, kp, 1);
            qp += __shfl_xor_sync(0xffffffffu, qp, 1);

            // acc += qp * sign(kp): flip qp's sign with kp's sign bit (NOT copysign);
            // jnp.sign(0) == 0 -> skip kp == 0.
            float t = __uint_as_float(__float_as_uint(qp) ^
                                      (__float_as_uint(kp) & 0x80000000u));
            if (kp != 0.0f) acc += t;
        }
    }

    if (half == 0 && token < ntok) {
        out[token] = (float)(1.2533141373155003 / 256.0) * acc;  // sqrt(pi/2)/NUM_PROJ
    }
}

extern "C" void kernel_launch(void* const* d_in, const int* in_sizes, int n_in,
                              void* d_out, int out_size) {
    // Identify S by element count (NPROJ*DIM = 32768); q precedes k among the rest.
    int s_idx = 2;
    for (int i = 0; i < n_in; ++i) if (in_sizes[i] == NPROJ * DIM) { s_idx = i; break; }
    int qk[2], w = 0;
    for (int i = 0; i < n_in && w < 2; ++i) if (i != s_idx) qk[w++] = i;

    const float* Q = (const float*)d_in[qk[0]];  // query [B,H,SEQ,DIM] fp32
    const float* K = (const float*)d_in[qk[1]];  // key   [B,H,SEQ,DIM] fp32
    const float* S = (const float*)d_in[s_idx];  // S     [NPROJ,DIM]   fp32
    float* out = (float*)d_out;                  // [B,H,SEQ] fp32

    const int ntok   = in_sizes[qk[0]] / DIM;
    const int blocks = (ntok + TOK_PER_BLOCK - 1) / TOK_PER_BLOCK;
    qjl_kernel<<<blocks, TPB>>>(Q, K, S, out, ntok);
}